// round 2
// baseline (speedup 1.0000x reference)
#include <cuda_runtime.h>
#include <cuda_bf16.h>
#include <math.h>

// Problem constants
#define BB 2
#define SS 2048
#define EE 1024
#define HH 16
#define DD 64
#define MTOT (BB*SS)        // 4096

// ---------------- scratch (no allocations allowed) ----------------
__device__ float g_q[BB*HH*SS*DD];     // [B,H,S,D]
__device__ float g_k[BB*HH*SS*DD];
__device__ float g_v[BB*HH*SS*DD];
__device__ float g_attn[MTOT*EE];      // [B,S,H*D]

// ---------------- SGEMM: C = A[M,K] @ B[K,N] (+bias), fp32 ----------------
// EPI=0: C[m*N+n] = acc + bias[n]
// EPI=1: scatter to [B,H,S,D]: m=b*S+s, n=h*D+d -> C[((b*H+h)*S+s)*D+d]
#define GBM 128
#define GBN 128
#define GBK 16

template <int EPI>
__global__ __launch_bounds__(256) void sgemm_kernel(
    const float* __restrict__ A, const float* __restrict__ Bm,
    const float* __restrict__ bias, float* __restrict__ C,
    int M, int N, int K)
{
    __shared__ float As[GBK][GBM];   // A stored transposed: As[k][m]
    __shared__ float Bs[GBK][GBN];

    const int tid = threadIdx.x;
    const int tx = tid & 15;         // 16 thread-cols
    const int ty = tid >> 4;         // 16 thread-rows
    const int bm = blockIdx.y * GBM;
    const int bn = blockIdx.x * GBN;

    float acc[8][8];
    #pragma unroll
    for (int i = 0; i < 8; i++)
        #pragma unroll
        for (int j = 0; j < 8; j++) acc[i][j] = 0.f;

    for (int k0 = 0; k0 < K; k0 += GBK) {
        // A tile: 128 rows x 16 cols = 512 float4
        #pragma unroll
        for (int v = tid; v < 512; v += 256) {
            int row = v >> 2;
            int c4  = (v & 3) * 4;
            float4 a = *reinterpret_cast<const float4*>(&A[(size_t)(bm + row) * K + k0 + c4]);
            As[c4 + 0][row] = a.x;
            As[c4 + 1][row] = a.y;
            As[c4 + 2][row] = a.z;
            As[c4 + 3][row] = a.w;
        }
        // B tile: 16 rows x 128 cols = 512 float4
        #pragma unroll
        for (int v = tid; v < 512; v += 256) {
            int krow = v >> 5;
            int c4   = (v & 31) * 4;
            *reinterpret_cast<float4*>(&Bs[krow][c4]) =
                *reinterpret_cast<const float4*>(&Bm[(size_t)(k0 + krow) * N + bn + c4]);
        }
        __syncthreads();

        #pragma unroll
        for (int kk = 0; kk < GBK; kk++) {
            float af[8], bf[8];
            #pragma unroll
            for (int i = 0; i < 8; i++) af[i] = As[kk][ty + i * 16];
            #pragma unroll
            for (int j = 0; j < 8; j++) bf[j] = Bs[kk][tx + j * 16];
            #pragma unroll
            for (int i = 0; i < 8; i++)
                #pragma unroll
                for (int j = 0; j < 8; j++)
                    acc[i][j] += af[i] * bf[j];
        }
        __syncthreads();
    }

    #pragma unroll
    for (int i = 0; i < 8; i++) {
        int m = bm + ty + i * 16;
        #pragma unroll
        for (int j = 0; j < 8; j++) {
            int n = bn + tx + j * 16;
            float val = acc[i][j];
            if (EPI == 0) {
                if (bias) val += bias[n];
                C[(size_t)m * N + n] = val;
            } else {
                int b = m >> 11;          // S = 2048
                int s = m & 2047;
                int h = n >> 6;           // D = 64
                int d = n & 63;
                C[((((size_t)b * HH + h) * SS) + s) * DD + d] = val;
            }
        }
    }
}

// ---------------- Flash attention (causal), fp32 ----------------
// One block per (q-tile of 128, head, batch). 256 threads.
// smem: Qs[128][65] Ks[64][65] Vs[64][65] Ss[128][65] + m/l/alpha[128]
#define FBQ 128
#define FBK 64
#define FLD 65
#define FLASH_SMEM ((FBQ*FLD + FBK*FLD + FBK*FLD + FBQ*FLD + 3*FBQ) * 4)

__global__ __launch_bounds__(256) void flash_kernel(
    const float* __restrict__ Q, const float* __restrict__ K,
    const float* __restrict__ V, float* __restrict__ O)
{
    extern __shared__ float sm[];
    float* Qs   = sm;
    float* Ks   = Qs + FBQ * FLD;
    float* Vs   = Ks + FBK * FLD;
    float* Ss   = Vs + FBK * FLD;
    float* mrow = Ss + FBQ * FLD;
    float* lrow = mrow + FBQ;
    float* arow = lrow + FBQ;

    const int tid = threadIdx.x;
    const int tx = tid & 15;
    const int ty = tid >> 4;
    const int q0 = blockIdx.x * FBQ;
    const int h  = blockIdx.y;
    const int b  = blockIdx.z;

    const float* qbase = Q + ((((size_t)b * HH + h) * SS) + q0) * DD;
    const float* kbase = K + (((size_t)b * HH + h) * SS) * DD;
    const float* vbase = V + (((size_t)b * HH + h) * SS) * DD;

    // Load Q tile: 128x64 = 2048 float4
    for (int v4 = tid; v4 < FBQ * DD / 4; v4 += 256) {
        int row = v4 >> 4;             // 16 float4 per row
        int c4  = (v4 & 15) * 4;
        float4 t = *reinterpret_cast<const float4*>(&qbase[row * DD + c4]);
        Qs[row * FLD + c4 + 0] = t.x;
        Qs[row * FLD + c4 + 1] = t.y;
        Qs[row * FLD + c4 + 2] = t.z;
        Qs[row * FLD + c4 + 3] = t.w;
    }
    if (tid < FBQ) { mrow[tid] = -1e30f; lrow[tid] = 0.f; }

    float oacc[8][4];
    #pragma unroll
    for (int i = 0; i < 8; i++)
        #pragma unroll
        for (int j = 0; j < 4; j++) oacc[i][j] = 0.f;

    const float scale = 0.125f;   // 1/sqrt(64)
    const int kend = q0 + FBQ;    // causal: keys < q0+128

    for (int k0 = 0; k0 < kend; k0 += FBK) {
        __syncthreads();   // protects Qs (1st iter) and Ks/Vs/Ss reuse (later iters)

        // Load K,V tiles: 64x64 each = 1024 float4 each
        for (int v4 = tid; v4 < FBK * DD / 4; v4 += 256) {
            int row = v4 >> 4;
            int c4  = (v4 & 15) * 4;
            float4 t = *reinterpret_cast<const float4*>(&kbase[(size_t)(k0 + row) * DD + c4]);
            Ks[row * FLD + c4 + 0] = t.x;
            Ks[row * FLD + c4 + 1] = t.y;
            Ks[row * FLD + c4 + 2] = t.z;
            Ks[row * FLD + c4 + 3] = t.w;
            float4 u = *reinterpret_cast<const float4*>(&vbase[(size_t)(k0 + row) * DD + c4]);
            Vs[row * FLD + c4 + 0] = u.x;
            Vs[row * FLD + c4 + 1] = u.y;
            Vs[row * FLD + c4 + 2] = u.z;
            Vs[row * FLD + c4 + 3] = u.w;
        }
        __syncthreads();

        // Scores: S[128,64] = Qs @ Ks^T
        float sacc[8][4];
        #pragma unroll
        for (int i = 0; i < 8; i++)
            #pragma unroll
            for (int j = 0; j < 4; j++) sacc[i][j] = 0.f;

        #pragma unroll 16
        for (int d = 0; d < DD; d++) {
            float af[8], bf[4];
            #pragma unroll
            for (int i = 0; i < 8; i++) af[i] = Qs[(ty + i * 16) * FLD + d];
            #pragma unroll
            for (int j = 0; j < 4; j++) bf[j] = Ks[(tx + j * 16) * FLD + d];
            #pragma unroll
            for (int i = 0; i < 8; i++)
                #pragma unroll
                for (int j = 0; j < 4; j++)
                    sacc[i][j] += af[i] * bf[j];
        }

        const bool needMask = (k0 + FBK - 1) > q0;
        #pragma unroll
        for (int i = 0; i < 8; i++) {
            int qg = q0 + ty + i * 16;
            #pragma unroll
            for (int j = 0; j < 4; j++) {
                int kg = k0 + tx + j * 16;
                float sv = sacc[i][j] * scale;
                if (needMask && kg > qg) sv = -1e30f;
                Ss[(ty + i * 16) * FLD + tx + j * 16] = sv;
            }
        }
        __syncthreads();

        // Online softmax per row (threads 0..127)
        if (tid < FBQ) {
            float mold = mrow[tid];
            float mt = mold;
            float* srow = &Ss[tid * FLD];
            #pragma unroll 16
            for (int j = 0; j < FBK; j++) mt = fmaxf(mt, srow[j]);
            float a = __expf(mold - mt);
            float ls = 0.f;
            #pragma unroll 16
            for (int j = 0; j < FBK; j++) {
                float e = __expf(srow[j] - mt);
                srow[j] = e;
                ls += e;
            }
            mrow[tid] = mt;
            lrow[tid] = lrow[tid] * a + ls;
            arow[tid] = a;
        }
        __syncthreads();

        // Rescale O, then O += P @ V
        float al[8];
        #pragma unroll
        for (int i = 0; i < 8; i++) al[i] = arow[ty + i * 16];
        #pragma unroll
        for (int i = 0; i < 8; i++)
            #pragma unroll
            for (int j = 0; j < 4; j++) oacc[i][j] *= al[i];

        #pragma unroll 16
        for (int kk = 0; kk < FBK; kk++) {
            float af[8], bf[4];
            #pragma unroll
            for (int i = 0; i < 8; i++) af[i] = Ss[(ty + i * 16) * FLD + kk];
            #pragma unroll
            for (int j = 0; j < 4; j++) bf[j] = Vs[kk * FLD + tx + j * 16];
            #pragma unroll
            for (int i = 0; i < 8; i++)
                #pragma unroll
                for (int j = 0; j < 4; j++)
                    oacc[i][j] += af[i] * bf[j];
        }
    }

    // Write out: O layout [B,S,H*D], normalize by l
    #pragma unroll
    for (int i = 0; i < 8; i++) {
        int row = ty + i * 16;
        float inv = 1.f / lrow[row];
        int s = q0 + row;
        #pragma unroll
        for (int j = 0; j < 4; j++) {
            int col = tx + j * 16;
            O[(((size_t)b * SS) + s) * EE + h * DD + col] = oacc[i][j] * inv;
        }
    }
}

// ---------------- launch ----------------
extern "C" void kernel_launch(void* const* d_in, const int* in_sizes, int n_in,
                              void* d_out, int out_size)
{
    const float* x  = (const float*)d_in[0];
    const float* Wq = (const float*)d_in[1];
    const float* Wk = (const float*)d_in[2];
    const float* Wv = (const float*)d_in[3];
    const float* Wp = (const float*)d_in[4];
    const float* bp = (const float*)d_in[5];
    float* out = (float*)d_out;

    float *q, *k, *v, *attn;
    cudaGetSymbolAddress((void**)&q,    g_q);
    cudaGetSymbolAddress((void**)&k,    g_k);
    cudaGetSymbolAddress((void**)&v,    g_v);
    cudaGetSymbolAddress((void**)&attn, g_attn);

    dim3 gridG(EE / GBN, MTOT / GBM);   // (8, 32)
    dim3 blockG(256);

    sgemm_kernel<1><<<gridG, blockG>>>(x, Wq, nullptr, q, MTOT, EE, EE);
    sgemm_kernel<1><<<gridG, blockG>>>(x, Wk, nullptr, k, MTOT, EE, EE);
    sgemm_kernel<1><<<gridG, blockG>>>(x, Wv, nullptr, v, MTOT, EE, EE);

    cudaFuncSetAttribute(flash_kernel, cudaFuncAttributeMaxDynamicSharedMemorySize, FLASH_SMEM);
    dim3 gridF(SS / FBQ, HH, BB);       // (16, 16, 2)
    flash_kernel<<<gridF, 256, FLASH_SMEM>>>(q, k, v, attn);

    sgemm_kernel<0><<<gridG, blockG>>>(attn, Wp, bp, out, MTOT, EE, EE);
}

// round 7
// speedup vs baseline: 1.7453x; 1.7453x over previous
#include <cuda_runtime.h>
#include <cuda_bf16.h>
#include <math.h>
#include <cstdint>

// Problem constants
#define BB 2
#define SS 2048
#define EE 1024
#define HH 16
#define DD 64
#define MTOT (BB*SS)        // 4096

// ---------------- scratch (no allocations allowed) ----------------
__device__ float g_q[BB*HH*SS*DD];     // [B,H,S,D]
__device__ float g_k[BB*HH*SS*DD];
__device__ float g_v[BB*HH*SS*DD];
__device__ float g_attn[MTOT*EE];      // [B,S,H*D]

// ---------------- helpers ----------------
__device__ __forceinline__ uint32_t f2tf32(float f) {
    uint32_t u;
    asm("cvt.rna.tf32.f32 %0, %1;" : "=r"(u) : "f"(f));
    return u;
}

__device__ __forceinline__ void mma_tf32(
    float& d0, float& d1, float& d2, float& d3,
    uint32_t a0, uint32_t a1, uint32_t a2, uint32_t a3,
    uint32_t b0, uint32_t b1)
{
    asm volatile(
        "mma.sync.aligned.m16n8k8.row.col.f32.tf32.tf32.f32 "
        "{%0,%1,%2,%3}, {%4,%5,%6,%7}, {%8,%9}, {%0,%1,%2,%3};"
        : "+f"(d0), "+f"(d1), "+f"(d2), "+f"(d3)
        : "r"(a0), "r"(a1), "r"(a2), "r"(a3), "r"(b0), "r"(b1));
}

// ============ tf32 mma.sync GEMM: C[4096,1024] = A @ W (+bias) ============
// CTA tile 128x128, BK=32, 256 threads = 8 warps (2 m x 4 n), warp tile 64x32.
// EPI=0: C[m*N+n] = acc + bias[n];  EPI=1: scatter to [B,H,S,D].
#define BKK 32
#define APITCH 36       // (4*tg+tr)%32 distinct -> conflict-free A frag LDS
#define BPITCH 136      // (8*tr+tg)%32 distinct -> conflict-free B frag LDS

template <int EPI>
__global__ __launch_bounds__(256, 2) void mma_gemm(
    const float* __restrict__ Ag, const float* __restrict__ Wg,
    const float* __restrict__ bias, float* __restrict__ C)
{
    __shared__ uint32_t As[128 * APITCH];   // As[m][k] tf32 bits
    __shared__ uint32_t Bs[BKK * BPITCH];   // Bs[k][n] tf32 bits

    const int tid  = threadIdx.x;
    const int warp = tid >> 5;
    const int lane = tid & 31;
    const int tg   = lane >> 2;     // 0..7
    const int tr   = lane & 3;      // 0..3
    const int wm   = (warp >> 2) * 64;   // 0 or 64
    const int wn   = (warp & 3) * 32;    // 0,32,64,96
    const int bm   = blockIdx.y * 128;
    const int bn   = blockIdx.x * 128;

    float acc[4][4][4];             // [mfrag][nfrag][reg]
    #pragma unroll
    for (int i = 0; i < 4; i++)
        #pragma unroll
        for (int j = 0; j < 4; j++)
            #pragma unroll
            for (int r = 0; r < 4; r++) acc[i][j][r] = 0.f;

    for (int k0 = 0; k0 < EE; k0 += BKK) {
        // ---- load A tile 128x32 (1024 float4, 4 per thread) ----
        #pragma unroll
        for (int i = 0; i < 4; i++) {
            int v   = tid + i * 256;
            int row = v >> 3;            // 8 float4 per row
            int c4  = (v & 7) * 4;
            float4 a = *reinterpret_cast<const float4*>(&Ag[(size_t)(bm + row) * EE + k0 + c4]);
            uint4 u;
            u.x = f2tf32(a.x); u.y = f2tf32(a.y); u.z = f2tf32(a.z); u.w = f2tf32(a.w);
            *reinterpret_cast<uint4*>(&As[row * APITCH + c4]) = u;
        }
        // ---- load B tile 32x128 (1024 float4, 4 per thread) ----
        #pragma unroll
        for (int i = 0; i < 4; i++) {
            int v   = tid + i * 256;
            int row = v >> 5;            // 32 float4 per row
            int c4  = (v & 31) * 4;
            float4 w = *reinterpret_cast<const float4*>(&Wg[(size_t)(k0 + row) * EE + bn + c4]);
            uint4 u;
            u.x = f2tf32(w.x); u.y = f2tf32(w.y); u.z = f2tf32(w.z); u.w = f2tf32(w.w);
            *reinterpret_cast<uint4*>(&Bs[row * BPITCH + c4]) = u;
        }
        __syncthreads();

        #pragma unroll
        for (int kk = 0; kk < BKK; kk += 8) {
            uint32_t afr[4][4];
            #pragma unroll
            for (int mi = 0; mi < 4; mi++) {
                int r = wm + mi * 16;
                afr[mi][0] = As[(r + tg    ) * APITCH + kk + tr    ];
                afr[mi][1] = As[(r + tg + 8) * APITCH + kk + tr    ];
                afr[mi][2] = As[(r + tg    ) * APITCH + kk + tr + 4];
                afr[mi][3] = As[(r + tg + 8) * APITCH + kk + tr + 4];
            }
            uint32_t bfr[4][2];
            #pragma unroll
            for (int nj = 0; nj < 4; nj++) {
                int c = wn + nj * 8 + tg;
                bfr[nj][0] = Bs[(kk + tr    ) * BPITCH + c];
                bfr[nj][1] = Bs[(kk + tr + 4) * BPITCH + c];
            }
            #pragma unroll
            for (int mi = 0; mi < 4; mi++)
                #pragma unroll
                for (int nj = 0; nj < 4; nj++)
                    mma_tf32(acc[mi][nj][0], acc[mi][nj][1], acc[mi][nj][2], acc[mi][nj][3],
                             afr[mi][0], afr[mi][1], afr[mi][2], afr[mi][3],
                             bfr[nj][0], bfr[nj][1]);
        }
        __syncthreads();
    }

    // ---- epilogue: direct float2 stores from fragments ----
    #pragma unroll
    for (int mi = 0; mi < 4; mi++) {
        #pragma unroll
        for (int nj = 0; nj < 4; nj++) {
            int n = bn + wn + nj * 8 + 2 * tr;
            #pragma unroll
            for (int half = 0; half < 2; half++) {
                int m = bm + wm + mi * 16 + tg + half * 8;
                float2 val;
                val.x = acc[mi][nj][half * 2 + 0];
                val.y = acc[mi][nj][half * 2 + 1];
                if (EPI == 0) {
                    val.x += bias[n + 0];
                    val.y += bias[n + 1];
                    *reinterpret_cast<float2*>(&C[(size_t)m * EE + n]) = val;
                } else {
                    int b = m >> 11;          // S = 2048
                    int s = m & 2047;
                    int h = n >> 6;           // D = 64; n even -> pair stays in head
                    int d = n & 63;
                    *reinterpret_cast<float2*>(
                        &C[((((size_t)b * HH + h) * SS) + s) * DD + d]) = val;
                }
            }
        }
    }
}

// ---------------- Flash attention (causal), fp32 — unchanged ----------------
#define FBQ 128
#define FBK 64
#define FLD 65
#define FLASH_SMEM ((FBQ*FLD + FBK*FLD + FBK*FLD + FBQ*FLD + 3*FBQ) * 4)

__global__ __launch_bounds__(256) void flash_kernel(
    const float* __restrict__ Q, const float* __restrict__ K,
    const float* __restrict__ V, float* __restrict__ O)
{
    extern __shared__ float sm[];
    float* Qs   = sm;
    float* Ks   = Qs + FBQ * FLD;
    float* Vs   = Ks + FBK * FLD;
    float* Ss   = Vs + FBK * FLD;
    float* mrow = Ss + FBQ * FLD;
    float* lrow = mrow + FBQ;
    float* arow = lrow + FBQ;

    const int tid = threadIdx.x;
    const int tx = tid & 15;
    const int ty = tid >> 4;
    const int q0 = blockIdx.x * FBQ;
    const int h  = blockIdx.y;
    const int b  = blockIdx.z;

    const float* qbase = Q + ((((size_t)b * HH + h) * SS) + q0) * DD;
    const float* kbase = K + (((size_t)b * HH + h) * SS) * DD;
    const float* vbase = V + (((size_t)b * HH + h) * SS) * DD;

    for (int v4 = tid; v4 < FBQ * DD / 4; v4 += 256) {
        int row = v4 >> 4;
        int c4  = (v4 & 15) * 4;
        float4 t = *reinterpret_cast<const float4*>(&qbase[row * DD + c4]);
        Qs[row * FLD + c4 + 0] = t.x;
        Qs[row * FLD + c4 + 1] = t.y;
        Qs[row * FLD + c4 + 2] = t.z;
        Qs[row * FLD + c4 + 3] = t.w;
    }
    if (tid < FBQ) { mrow[tid] = -1e30f; lrow[tid] = 0.f; }

    float oacc[8][4];
    #pragma unroll
    for (int i = 0; i < 8; i++)
        #pragma unroll
        for (int j = 0; j < 4; j++) oacc[i][j] = 0.f;

    const float scale = 0.125f;
    const int kend = q0 + FBQ;

    for (int k0 = 0; k0 < kend; k0 += FBK) {
        __syncthreads();

        for (int v4 = tid; v4 < FBK * DD / 4; v4 += 256) {
            int row = v4 >> 4;
            int c4  = (v4 & 15) * 4;
            float4 t = *reinterpret_cast<const float4*>(&kbase[(size_t)(k0 + row) * DD + c4]);
            Ks[row * FLD + c4 + 0] = t.x;
            Ks[row * FLD + c4 + 1] = t.y;
            Ks[row * FLD + c4 + 2] = t.z;
            Ks[row * FLD + c4 + 3] = t.w;
            float4 u = *reinterpret_cast<const float4*>(&vbase[(size_t)(k0 + row) * DD + c4]);
            Vs[row * FLD + c4 + 0] = u.x;
            Vs[row * FLD + c4 + 1] = u.y;
            Vs[row * FLD + c4 + 2] = u.z;
            Vs[row * FLD + c4 + 3] = u.w;
        }
        __syncthreads();

        float sacc[8][4];
        #pragma unroll
        for (int i = 0; i < 8; i++)
            #pragma unroll
            for (int j = 0; j < 4; j++) sacc[i][j] = 0.f;

        #pragma unroll 16
        for (int d = 0; d < DD; d++) {
            float af[8], bf[4];
            #pragma unroll
            for (int i = 0; i < 8; i++) af[i] = Qs[(ty + i * 16) * FLD + d];
            #pragma unroll
            for (int j = 0; j < 4; j++) bf[j] = Ks[(tx + j * 16) * FLD + d];
            #pragma unroll
            for (int i = 0; i < 8; i++)
                #pragma unroll
                for (int j = 0; j < 4; j++)
                    sacc[i][j] += af[i] * bf[j];
        }

        const bool needMask = (k0 + FBK - 1) > q0;
        #pragma unroll
        for (int i = 0; i < 8; i++) {
            int qg = q0 + ty + i * 16;
            #pragma unroll
            for (int j = 0; j < 4; j++) {
                int kg = k0 + tx + j * 16;
                float sv = sacc[i][j] * scale;
                if (needMask && kg > qg) sv = -1e30f;
                Ss[(ty + i * 16) * FLD + tx + j * 16] = sv;
            }
        }
        __syncthreads();

        if (tid < FBQ) {
            float mold = mrow[tid];
            float mt = mold;
            float* srow = &Ss[tid * FLD];
            #pragma unroll 16
            for (int j = 0; j < FBK; j++) mt = fmaxf(mt, srow[j]);
            float a = __expf(mold - mt);
            float ls = 0.f;
            #pragma unroll 16
            for (int j = 0; j < FBK; j++) {
                float e = __expf(srow[j] - mt);
                srow[j] = e;
                ls += e;
            }
            mrow[tid] = mt;
            lrow[tid] = lrow[tid] * a + ls;
            arow[tid] = a;
        }
        __syncthreads();

        float al[8];
        #pragma unroll
        for (int i = 0; i < 8; i++) al[i] = arow[ty + i * 16];
        #pragma unroll
        for (int i = 0; i < 8; i++)
            #pragma unroll
            for (int j = 0; j < 4; j++) oacc[i][j] *= al[i];

        #pragma unroll 16
        for (int kk = 0; kk < FBK; kk++) {
            float af[8], bf[4];
            #pragma unroll
            for (int i = 0; i < 8; i++) af[i] = Ss[(ty + i * 16) * FLD + kk];
            #pragma unroll
            for (int j = 0; j < 4; j++) bf[j] = Vs[kk * FLD + tx + j * 16];
            #pragma unroll
            for (int i = 0; i < 8; i++)
                #pragma unroll
                for (int j = 0; j < 4; j++)
                    oacc[i][j] += af[i] * bf[j];
        }
    }

    #pragma unroll
    for (int i = 0; i < 8; i++) {
        int row = ty + i * 16;
        float inv = 1.f / lrow[row];
        int s = q0 + row;
        #pragma unroll
        for (int j = 0; j < 4; j++) {
            int col = tx + j * 16;
            O[(((size_t)b * SS) + s) * EE + h * DD + col] = oacc[i][j] * inv;
        }
    }
}

// ---------------- launch ----------------
extern "C" void kernel_launch(void* const* d_in, const int* in_sizes, int n_in,
                              void* d_out, int out_size)
{
    const float* x  = (const float*)d_in[0];
    const float* Wq = (const float*)d_in[1];
    const float* Wk = (const float*)d_in[2];
    const float* Wv = (const float*)d_in[3];
    const float* Wp = (const float*)d_in[4];
    const float* bp = (const float*)d_in[5];
    float* out = (float*)d_out;

    float *q, *k, *v, *attn;
    cudaGetSymbolAddress((void**)&q,    g_q);
    cudaGetSymbolAddress((void**)&k,    g_k);
    cudaGetSymbolAddress((void**)&v,    g_v);
    cudaGetSymbolAddress((void**)&attn, g_attn);

    dim3 gridG(EE / 128, MTOT / 128);   // (8, 32)

    mma_gemm<1><<<gridG, 256>>>(x, Wq, nullptr, q);
    mma_gemm<1><<<gridG, 256>>>(x, Wk, nullptr, k);
    mma_gemm<1><<<gridG, 256>>>(x, Wv, nullptr, v);

    cudaFuncSetAttribute(flash_kernel, cudaFuncAttributeMaxDynamicSharedMemorySize, FLASH_SMEM);
    dim3 gridF(SS / FBQ, HH, BB);       // (16, 16, 2)
    flash_kernel<<<gridF, 256, FLASH_SMEM>>>(q, k, v, attn);

    mma_gemm<0><<<gridG, 256>>>(attn, Wp, bp, out);
}

// round 16
// speedup vs baseline: 3.0002x; 1.7190x over previous
#include <cuda_runtime.h>
#include <cuda_bf16.h>
#include <math.h>
#include <cstdint>

// Problem constants
#define BB 2
#define SS 2048
#define EE 1024
#define HH 16
#define DD 64
#define MTOT (BB*SS)        // 4096

// ---------------- scratch (no allocations allowed) ----------------
__device__ float g_q[BB*HH*SS*DD];     // [B,H,S,D]
__device__ float g_k[BB*HH*SS*DD];
__device__ float g_v[BB*HH*SS*DD];
__device__ float g_attn[MTOT*EE];      // [B,S,H*D]

// ---------------- helpers ----------------
__device__ __forceinline__ uint32_t f2tf32(float f) {
    uint32_t u;
    asm("cvt.rna.tf32.f32 %0, %1;" : "=r"(u) : "f"(f));
    return u;
}

__device__ __forceinline__ void mma_tf32(
    float& d0, float& d1, float& d2, float& d3,
    uint32_t a0, uint32_t a1, uint32_t a2, uint32_t a3,
    uint32_t b0, uint32_t b1)
{
    asm volatile(
        "mma.sync.aligned.m16n8k8.row.col.f32.tf32.tf32.f32 "
        "{%0,%1,%2,%3}, {%4,%5,%6,%7}, {%8,%9}, {%0,%1,%2,%3};"
        : "+f"(d0), "+f"(d1), "+f"(d2), "+f"(d3)
        : "r"(a0), "r"(a1), "r"(a2), "r"(a3), "r"(b0), "r"(b1));
}

// ============ tf32 mma.sync GEMM: C[4096,1024] = A @ W (+bias) ============
#define BKK 32
#define APITCH 36
#define BPITCH 136

template <int EPI>
__global__ __launch_bounds__(256, 2) void mma_gemm(
    const float* __restrict__ Ag, const float* __restrict__ Wg,
    const float* __restrict__ bias, float* __restrict__ C)
{
    __shared__ uint32_t As[128 * APITCH];
    __shared__ uint32_t Bs[BKK * BPITCH];

    const int tid  = threadIdx.x;
    const int warp = tid >> 5;
    const int lane = tid & 31;
    const int tg   = lane >> 2;
    const int tr   = lane & 3;
    const int wm   = (warp >> 2) * 64;
    const int wn   = (warp & 3) * 32;
    const int bm   = blockIdx.y * 128;
    const int bn   = blockIdx.x * 128;

    float acc[4][4][4];
    #pragma unroll
    for (int i = 0; i < 4; i++)
        #pragma unroll
        for (int j = 0; j < 4; j++)
            #pragma unroll
            for (int r = 0; r < 4; r++) acc[i][j][r] = 0.f;

    for (int k0 = 0; k0 < EE; k0 += BKK) {
        #pragma unroll
        for (int i = 0; i < 4; i++) {
            int v   = tid + i * 256;
            int row = v >> 3;
            int c4  = (v & 7) * 4;
            float4 a = *reinterpret_cast<const float4*>(&Ag[(size_t)(bm + row) * EE + k0 + c4]);
            uint4 u;
            u.x = f2tf32(a.x); u.y = f2tf32(a.y); u.z = f2tf32(a.z); u.w = f2tf32(a.w);
            *reinterpret_cast<uint4*>(&As[row * APITCH + c4]) = u;
        }
        #pragma unroll
        for (int i = 0; i < 4; i++) {
            int v   = tid + i * 256;
            int row = v >> 5;
            int c4  = (v & 31) * 4;
            float4 w = *reinterpret_cast<const float4*>(&Wg[(size_t)(k0 + row) * EE + bn + c4]);
            uint4 u;
            u.x = f2tf32(w.x); u.y = f2tf32(w.y); u.z = f2tf32(w.z); u.w = f2tf32(w.w);
            *reinterpret_cast<uint4*>(&Bs[row * BPITCH + c4]) = u;
        }
        __syncthreads();

        #pragma unroll
        for (int kk = 0; kk < BKK; kk += 8) {
            uint32_t afr[4][4];
            #pragma unroll
            for (int mi = 0; mi < 4; mi++) {
                int r = wm + mi * 16;
                afr[mi][0] = As[(r + tg    ) * APITCH + kk + tr    ];
                afr[mi][1] = As[(r + tg + 8) * APITCH + kk + tr    ];
                afr[mi][2] = As[(r + tg    ) * APITCH + kk + tr + 4];
                afr[mi][3] = As[(r + tg + 8) * APITCH + kk + tr + 4];
            }
            uint32_t bfr[4][2];
            #pragma unroll
            for (int nj = 0; nj < 4; nj++) {
                int c = wn + nj * 8 + tg;
                bfr[nj][0] = Bs[(kk + tr    ) * BPITCH + c];
                bfr[nj][1] = Bs[(kk + tr + 4) * BPITCH + c];
            }
            #pragma unroll
            for (int mi = 0; mi < 4; mi++)
                #pragma unroll
                for (int nj = 0; nj < 4; nj++)
                    mma_tf32(acc[mi][nj][0], acc[mi][nj][1], acc[mi][nj][2], acc[mi][nj][3],
                             afr[mi][0], afr[mi][1], afr[mi][2], afr[mi][3],
                             bfr[nj][0], bfr[nj][1]);
        }
        __syncthreads();
    }

    #pragma unroll
    for (int mi = 0; mi < 4; mi++) {
        #pragma unroll
        for (int nj = 0; nj < 4; nj++) {
            int n = bn + wn + nj * 8 + 2 * tr;
            #pragma unroll
            for (int half = 0; half < 2; half++) {
                int m = bm + wm + mi * 16 + tg + half * 8;
                float2 val;
                val.x = acc[mi][nj][half * 2 + 0];
                val.y = acc[mi][nj][half * 2 + 1];
                if (EPI == 0) {
                    val.x += bias[n + 0];
                    val.y += bias[n + 1];
                    *reinterpret_cast<float2*>(&C[(size_t)m * EE + n]) = val;
                } else {
                    int b = m >> 11;
                    int s = m & 2047;
                    int h = n >> 6;
                    int d = n & 63;
                    *reinterpret_cast<float2*>(
                        &C[((((size_t)b * HH + h) * SS) + s) * DD + d]) = val;
                }
            }
        }
    }
}

// ========== tensor-core flash attention (causal), tf32 mma.sync ==========
// Block: 128 q-rows, 256 threads = 8 warps, each warp owns 16 q-rows.
// KV tile = 64. Q frags in registers; S softmax in register C-frags;
// P staged via smem (own-warp rows only); O accumulated in C-frags.
#define FP 68   // smem pitch (words): conflict-free frag access patterns
#define FL2_SMEM ((64*FP + 64*FP + 128*FP) * 4)   // Ks + Vs + Ps = 69632 B

__global__ __launch_bounds__(256) void flash_mma(
    const float* __restrict__ Q, const float* __restrict__ K,
    const float* __restrict__ V, float* __restrict__ O)
{
    extern __shared__ uint32_t sm2[];
    uint32_t* Ks = sm2;            // [64][FP] tf32 bits, K[kv][d]
    uint32_t* Vs = Ks + 64 * FP;   // [64][FP] tf32 bits, V[kv][d]
    uint32_t* Ps = Vs + 64 * FP;   // [128][FP] tf32 bits; Q staging then P

    const int tid  = threadIdx.x;
    const int warp = tid >> 5;
    const int lane = tid & 31;
    const int tg   = lane >> 2;    // 0..7
    const int tr   = lane & 3;     // 0..3
    const int q0   = blockIdx.x * 128;
    const int h    = blockIdx.y;
    const int b    = blockIdx.z;
    const int wr   = warp * 16;    // warp's q-row offset in tile

    const float* qbase = Q + (((size_t)b * HH + h) * SS + q0) * DD;
    const float* kbase = K + (((size_t)b * HH + h) * SS) * DD;
    const float* vbase = V + (((size_t)b * HH + h) * SS) * DD;

    // ---- stage Q (pre-scaled by 1/sqrt(D), tf32) into Ps ----
    for (int v4 = tid; v4 < 128 * DD / 4; v4 += 256) {
        int row = v4 >> 4;
        int c4  = (v4 & 15) * 4;
        float4 t = *reinterpret_cast<const float4*>(&qbase[row * DD + c4]);
        uint4 u;
        u.x = f2tf32(t.x * 0.125f); u.y = f2tf32(t.y * 0.125f);
        u.z = f2tf32(t.z * 0.125f); u.w = f2tf32(t.w * 0.125f);
        *reinterpret_cast<uint4*>(&Ps[row * FP + c4]) = u;
    }
    __syncthreads();

    // ---- extract Q A-frags: qf[kk][0..3], kk = d/8 ----
    uint32_t qf[8][4];
    #pragma unroll
    for (int kk = 0; kk < 8; kk++) {
        qf[kk][0] = Ps[(wr + tg    ) * FP + kk * 8 + tr    ];
        qf[kk][1] = Ps[(wr + tg + 8) * FP + kk * 8 + tr    ];
        qf[kk][2] = Ps[(wr + tg    ) * FP + kk * 8 + tr + 4];
        qf[kk][3] = Ps[(wr + tg + 8) * FP + kk * 8 + tr + 4];
    }

    float oacc[8][4];
    #pragma unroll
    for (int nj = 0; nj < 8; nj++)
        #pragma unroll
        for (int r = 0; r < 4; r++) oacc[nj][r] = 0.f;
    float mrow[2] = {-1e30f, -1e30f};
    float lrow[2] = {0.f, 0.f};

    for (int k0 = 0; k0 < q0 + 128; k0 += 64) {
        __syncthreads();   // all warps done with prior Ks/Vs (and Ps Q-staging on iter 0)

        // ---- load K,V tile 64x64 each (tf32) ----
        for (int v4 = tid; v4 < 64 * DD / 4; v4 += 256) {
            int row = v4 >> 4;
            int c4  = (v4 & 15) * 4;
            float4 t = *reinterpret_cast<const float4*>(&kbase[(size_t)(k0 + row) * DD + c4]);
            uint4 uk;
            uk.x = f2tf32(t.x); uk.y = f2tf32(t.y); uk.z = f2tf32(t.z); uk.w = f2tf32(t.w);
            *reinterpret_cast<uint4*>(&Ks[row * FP + c4]) = uk;
            float4 u = *reinterpret_cast<const float4*>(&vbase[(size_t)(k0 + row) * DD + c4]);
            uint4 uv;
            uv.x = f2tf32(u.x); uv.y = f2tf32(u.y); uv.z = f2tf32(u.z); uv.w = f2tf32(u.w);
            *reinterpret_cast<uint4*>(&Vs[row * FP + c4]) = uv;
        }
        __syncthreads();

        // ---- S = Q @ K^T : sacc[nj] covers kv cols nj*8..nj*8+7 ----
        float sacc[8][4];
        #pragma unroll
        for (int nj = 0; nj < 8; nj++)
            #pragma unroll
            for (int r = 0; r < 4; r++) sacc[nj][r] = 0.f;

        #pragma unroll
        for (int kk = 0; kk < 8; kk++) {
            #pragma unroll
            for (int nj = 0; nj < 8; nj++) {
                uint32_t b0 = Ks[(nj * 8 + tg) * FP + kk * 8 + tr    ];
                uint32_t b1 = Ks[(nj * 8 + tg) * FP + kk * 8 + tr + 4];
                mma_tf32(sacc[nj][0], sacc[nj][1], sacc[nj][2], sacc[nj][3],
                         qf[kk][0], qf[kk][1], qf[kk][2], qf[kk][3], b0, b1);
            }
        }

        // ---- causal mask ----
        if (k0 + 64 > q0 + wr) {
            #pragma unroll
            for (int nj = 0; nj < 8; nj++) {
                #pragma unroll
                for (int r = 0; r < 4; r++) {
                    int qrow = q0 + wr + tg + ((r >> 1) << 3);
                    int kcol = k0 + nj * 8 + 2 * tr + (r & 1);
                    if (kcol > qrow) sacc[nj][r] = -1e30f;
                }
            }
        }

        // ---- online softmax (rows tg -> half 0 regs {0,1}; tg+8 -> half 1 regs {2,3}) ----
        #pragma unroll
        for (int half = 0; half < 2; half++) {
            float mloc = -1e30f;
            #pragma unroll
            for (int nj = 0; nj < 8; nj++) {
                mloc = fmaxf(mloc, sacc[nj][half * 2 + 0]);
                mloc = fmaxf(mloc, sacc[nj][half * 2 + 1]);
            }
            mloc = fmaxf(mloc, __shfl_xor_sync(0xffffffffu, mloc, 1));
            mloc = fmaxf(mloc, __shfl_xor_sync(0xffffffffu, mloc, 2));
            float mnew  = fmaxf(mrow[half], mloc);
            float alpha = __expf(mrow[half] - mnew);
            float ls = 0.f;
            #pragma unroll
            for (int nj = 0; nj < 8; nj++) {
                float p0 = __expf(sacc[nj][half * 2 + 0] - mnew);
                float p1 = __expf(sacc[nj][half * 2 + 1] - mnew);
                sacc[nj][half * 2 + 0] = p0;
                sacc[nj][half * 2 + 1] = p1;
                ls += p0 + p1;
            }
            ls += __shfl_xor_sync(0xffffffffu, ls, 1);
            ls += __shfl_xor_sync(0xffffffffu, ls, 2);
            mrow[half] = mnew;
            lrow[half] = lrow[half] * alpha + ls;
            #pragma unroll
            for (int nj = 0; nj < 8; nj++) {
                oacc[nj][half * 2 + 0] *= alpha;
                oacc[nj][half * 2 + 1] *= alpha;
            }
            // stage P (own warp rows only)
            int prow = (wr + tg + half * 8) * FP;
            #pragma unroll
            for (int nj = 0; nj < 8; nj++) {
                Ps[prow + nj * 8 + 2 * tr    ] = f2tf32(sacc[nj][half * 2 + 0]);
                Ps[prow + nj * 8 + 2 * tr + 1] = f2tf32(sacc[nj][half * 2 + 1]);
            }
        }
        __syncwarp();   // P rows written by own warp's lanes; order before A-frag reads

        // ---- O += P @ V ----
        #pragma unroll
        for (int kk = 0; kk < 8; kk++) {
            uint32_t a0 = Ps[(wr + tg    ) * FP + kk * 8 + tr    ];
            uint32_t a1 = Ps[(wr + tg + 8) * FP + kk * 8 + tr    ];
            uint32_t a2 = Ps[(wr + tg    ) * FP + kk * 8 + tr + 4];
            uint32_t a3 = Ps[(wr + tg + 8) * FP + kk * 8 + tr + 4];
            #pragma unroll
            for (int nj = 0; nj < 8; nj++) {
                uint32_t b0 = Vs[(kk * 8 + tr    ) * FP + nj * 8 + tg];
                uint32_t b1 = Vs[(kk * 8 + tr + 4) * FP + nj * 8 + tg];
                mma_tf32(oacc[nj][0], oacc[nj][1], oacc[nj][2], oacc[nj][3],
                         a0, a1, a2, a3, b0, b1);
            }
        }
    }

    // ---- write O to [B,S,H*D], normalized ----
    #pragma unroll
    for (int half = 0; half < 2; half++) {
        int s = q0 + wr + tg + half * 8;
        float inv = 1.f / lrow[half];
        #pragma unroll
        for (int nj = 0; nj < 8; nj++) {
            float2 val;
            val.x = oacc[nj][half * 2 + 0] * inv;
            val.y = oacc[nj][half * 2 + 1] * inv;
            *reinterpret_cast<float2*>(
                &O[((size_t)b * SS + s) * EE + h * DD + nj * 8 + 2 * tr]) = val;
        }
    }
}

// ---------------- launch ----------------
extern "C" void kernel_launch(void* const* d_in, const int* in_sizes, int n_in,
                              void* d_out, int out_size)
{
    const float* x  = (const float*)d_in[0];
    const float* Wq = (const float*)d_in[1];
    const float* Wk = (const float*)d_in[2];
    const float* Wv = (const float*)d_in[3];
    const float* Wp = (const float*)d_in[4];
    const float* bp = (const float*)d_in[5];
    float* out = (float*)d_out;

    float *q, *k, *v, *attn;
    cudaGetSymbolAddress((void**)&q,    g_q);
    cudaGetSymbolAddress((void**)&k,    g_k);
    cudaGetSymbolAddress((void**)&v,    g_v);
    cudaGetSymbolAddress((void**)&attn, g_attn);

    dim3 gridG(EE / 128, MTOT / 128);   // (8, 32)

    mma_gemm<1><<<gridG, 256>>>(x, Wq, nullptr, q);
    mma_gemm<1><<<gridG, 256>>>(x, Wk, nullptr, k);
    mma_gemm<1><<<gridG, 256>>>(x, Wv, nullptr, v);

    cudaFuncSetAttribute(flash_mma, cudaFuncAttributeMaxDynamicSharedMemorySize, FL2_SMEM);
    dim3 gridF(SS / 128, HH, BB);       // (16, 16, 2)
    flash_mma<<<gridF, 256, FL2_SMEM>>>(q, k, v, attn);

    mma_gemm<0><<<gridG, 256>>>(attn, Wp, bp, out);
}